// round 12
// baseline (speedup 1.0000x reference)
#include <cuda_runtime.h>
#include <math.h>
#include <stdint.h>

#define BATCH 65536
#define IN_DIM 64
#define HID 128
#define CHOL 136
#define FULLM 0xffffffffu

// Scratch
__device__ float g_h1[BATCH * HID];
__device__ float g_h2[BATCH * HID];
__device__ float g_ld[BATCH * CHOL];

// ---------------------------------------------------------------------------
// Tensor-core SGEMM via tf32 mma.sync with x3 precision split, hi/lo pre-split
// into smem at staging so the inner loop is pure LDS + MMA.
//   C[M,N] = act(A[M,K] @ W[K,N] + b),  ACT: 0 = LeakyReLU(0.01), 1 = tanh.
// Block = 128 threads (4 warps), tile 64(M) x 64(N), K-chunk 16.
// ---------------------------------------------------------------------------
__device__ __forceinline__ void mma_tf32(float* c, uint32_t a0, uint32_t a1,
                                         uint32_t a2, uint32_t a3,
                                         uint32_t b0, uint32_t b1)
{
    asm volatile(
        "mma.sync.aligned.m16n8k8.row.col.f32.tf32.tf32.f32 "
        "{%0,%1,%2,%3}, {%4,%5,%6,%7}, {%8,%9}, {%0,%1,%2,%3};\n"
        : "+f"(c[0]), "+f"(c[1]), "+f"(c[2]), "+f"(c[3])
        : "r"(a0), "r"(a1), "r"(a2), "r"(a3), "r"(b0), "r"(b1));
}

__device__ __forceinline__ void split_tf32(float v, float& hi, float& lo)
{
    uint32_t u = __float_as_uint(v) & 0xffffe000u;
    hi = __uint_as_float(u);
    float rem = v - hi;
    lo = __uint_as_float(__float_as_uint(rem) & 0xffffe000u);
}

template<int ACT>
__global__ __launch_bounds__(128) void gemm_tf32(
    const float* __restrict__ A, const float* __restrict__ W,
    const float* __restrict__ bias, float* __restrict__ C,
    int M, int N, int K)
{
    __shared__ float sAh[64][20], sAl[64][20];   // [m][k] hi/lo
    __shared__ float sWh[16][72], sWl[16][72];   // [k][n] hi/lo

    const int tid  = threadIdx.x;
    const int warp = tid >> 5, lane = tid & 31;
    const int grp  = lane >> 2, tig = lane & 3;
    const int bm   = blockIdx.x * 64, bn = blockIdx.y * 64;
    const int wrow = warp * 16;

    const int ntmax = min(8, (N - bn + 7) >> 3);

    float c[8][4];
    #pragma unroll
    for (int t = 0; t < 8; t++)
        #pragma unroll
        for (int j = 0; j < 4; j++) c[t][j] = 0.f;

    for (int k0 = 0; k0 < K; k0 += 16) {
        // Stage A 64x16 split (2 float4 per thread).
        #pragma unroll
        for (int i = 0; i < 2; i++) {
            int idx = tid + i * 128;
            int row = idx >> 2, k4 = (idx & 3) * 4;
            float4 v = *(const float4*)&A[(size_t)(bm + row) * K + k0 + k4];
            float4 h, l;
            split_tf32(v.x, h.x, l.x); split_tf32(v.y, h.y, l.y);
            split_tf32(v.z, h.z, l.z); split_tf32(v.w, h.w, l.w);
            *(float4*)&sAh[row][k4] = h;
            *(float4*)&sAl[row][k4] = l;
        }
        // Stage W 16x64 split (2 float4 per thread), zero-pad N tail.
        #pragma unroll
        for (int i = 0; i < 2; i++) {
            int idx = tid + i * 128;
            int kk = idx >> 4, c4 = (idx & 15) * 4;
            const float* wr = &W[(size_t)(k0 + kk) * N];
            int gc = bn + c4;
            float4 v;
            v.x = (gc + 0 < N) ? wr[gc + 0] : 0.f;
            v.y = (gc + 1 < N) ? wr[gc + 1] : 0.f;
            v.z = (gc + 2 < N) ? wr[gc + 2] : 0.f;
            v.w = (gc + 3 < N) ? wr[gc + 3] : 0.f;
            float4 h, l;
            split_tf32(v.x, h.x, l.x); split_tf32(v.y, h.y, l.y);
            split_tf32(v.z, h.z, l.z); split_tf32(v.w, h.w, l.w);
            *(float4*)&sWh[kk][c4] = h;
            *(float4*)&sWl[kk][c4] = l;
        }
        __syncthreads();

        #pragma unroll
        for (int k8 = 0; k8 < 16; k8 += 8) {
            uint32_t ah0 = __float_as_uint(sAh[wrow + grp    ][k8 + tig    ]);
            uint32_t ah1 = __float_as_uint(sAh[wrow + grp + 8][k8 + tig    ]);
            uint32_t ah2 = __float_as_uint(sAh[wrow + grp    ][k8 + tig + 4]);
            uint32_t ah3 = __float_as_uint(sAh[wrow + grp + 8][k8 + tig + 4]);
            uint32_t al0 = __float_as_uint(sAl[wrow + grp    ][k8 + tig    ]);
            uint32_t al1 = __float_as_uint(sAl[wrow + grp + 8][k8 + tig    ]);
            uint32_t al2 = __float_as_uint(sAl[wrow + grp    ][k8 + tig + 4]);
            uint32_t al3 = __float_as_uint(sAl[wrow + grp + 8][k8 + tig + 4]);

            for (int nt = 0; nt < ntmax; nt++) {
                uint32_t bh0 = __float_as_uint(sWh[k8 + tig    ][nt * 8 + grp]);
                uint32_t bh1 = __float_as_uint(sWh[k8 + tig + 4][nt * 8 + grp]);
                uint32_t bl0 = __float_as_uint(sWl[k8 + tig    ][nt * 8 + grp]);
                uint32_t bl1 = __float_as_uint(sWl[k8 + tig + 4][nt * 8 + grp]);

                mma_tf32(c[nt], ah0, ah1, ah2, ah3, bh0, bh1);
                mma_tf32(c[nt], ah0, ah1, ah2, ah3, bl0, bl1);
                mma_tf32(c[nt], al0, al1, al2, al3, bh0, bh1);
            }
        }
        __syncthreads();
    }

    // Epilogue: c[nt] regs -> rows (grp, grp+8), cols (2*tig, 2*tig+1).
    const int r0 = bm + wrow + grp;
    for (int nt = 0; nt < ntmax; nt++) {
        int col = bn + nt * 8 + 2 * tig;
        if (col >= N) continue;
        bool c2ok = (col + 1 < N);
        float b0v = bias[col];
        float b1v = c2ok ? bias[col + 1] : 0.f;
        #pragma unroll
        for (int h = 0; h < 2; h++) {
            float v0 = c[nt][2 * h + 0] + b0v;
            float v1 = c[nt][2 * h + 1] + b1v;
            if (ACT == 0) {
                v0 = (v0 > 0.f) ? v0 : 0.01f * v0;
                v1 = (v1 > 0.f) ? v1 : 0.01f * v1;
            } else {
                v0 = tanhf(v0); v1 = tanhf(v1);
            }
            float* cp = &C[(size_t)(r0 + 8 * h) * N + col];
            if (c2ok) { cp[0] = v0; cp[1] = v1; }
            else      { cp[0] = v0; }
        }
    }
}

// ---------------------------------------------------------------------------
// Eigendecomposition-free PSD head, fused polynomial form:
//   out = Ct / sqrt(tr(Ct^2)),  Ct = exp(M),
//   M = (exp(2Q)-I)/2 ~= Q + Q^2 + (2/3)Q^3 + (1/3)Q^4
//     = Q(I + Q(I + Q((2/3)I + (1/3)Q)))            [3 matvecs]
// then exp(M) by degree-4 Taylor Horner              [3 matvecs]
// 8 lanes per matrix, 2 columns per lane, row-at-a-time matvec (unroll 1),
// T bounce in smem.
// ---------------------------------------------------------------------------
#define RST 16
#define MST 520     // X(256) + T(256) + 8 pad
#define NTERMS 4

__constant__ float c_invk[NTERMS] = {0.f, 1.f, 0.5f, 1.f/3.f};

__device__ __forceinline__ void matvec2(const float* __restrict__ X,
                                        const float* __restrict__ s0,
                                        const float* __restrict__ s1,
                                        float2* __restrict__ T2, int l)
{
    #pragma unroll 1
    for (int r = 0; r < 16; r++) {
        const float4* row = (const float4*)(X + r * RST);
        float4 x0 = row[0], x1 = row[1], x2 = row[2], x3 = row[3];
        float a0 = x0.x * s0[0],  b0 = x0.y * s0[1];
        float a1 = x0.x * s1[0],  b1 = x0.y * s1[1];
        a0 = fmaf(x0.z, s0[2],  a0);  b0 = fmaf(x0.w, s0[3],  b0);
        a1 = fmaf(x0.z, s1[2],  a1);  b1 = fmaf(x0.w, s1[3],  b1);
        a0 = fmaf(x1.x, s0[4],  a0);  b0 = fmaf(x1.y, s0[5],  b0);
        a1 = fmaf(x1.x, s1[4],  a1);  b1 = fmaf(x1.y, s1[5],  b1);
        a0 = fmaf(x1.z, s0[6],  a0);  b0 = fmaf(x1.w, s0[7],  b0);
        a1 = fmaf(x1.z, s1[6],  a1);  b1 = fmaf(x1.w, s1[7],  b1);
        a0 = fmaf(x2.x, s0[8],  a0);  b0 = fmaf(x2.y, s0[9],  b0);
        a1 = fmaf(x2.x, s1[8],  a1);  b1 = fmaf(x2.y, s1[9],  b1);
        a0 = fmaf(x2.z, s0[10], a0);  b0 = fmaf(x2.w, s0[11], b0);
        a1 = fmaf(x2.z, s1[10], a1);  b1 = fmaf(x2.w, s1[11], b1);
        a0 = fmaf(x3.x, s0[12], a0);  b0 = fmaf(x3.y, s0[13], b0);
        a1 = fmaf(x3.x, s1[12], a1);  b1 = fmaf(x3.y, s1[13], b1);
        a0 = fmaf(x3.z, s0[14], a0);  b0 = fmaf(x3.w, s0[15], b0);
        a1 = fmaf(x3.z, s1[14], a1);  b1 = fmaf(x3.w, s1[15], b1);
        T2[r * 8 + l] = make_float2(a0 + b0, a1 + b1);
    }
}

__global__ __launch_bounds__(128, 6) void psd_expm(
    const float* __restrict__ ldata, float* __restrict__ out)
{
    __shared__ __align__(16) float sh[16 * MST];
    const int tid = threadIdx.x;
    const int g   = tid >> 3;
    const int l   = tid & 7;
    const int b   = blockIdx.x * 16 + g;
    float* X  = sh + g * MST;
    float* T  = X + 256;
    float2* X2 = (float2*)X;
    float2* T2 = (float2*)T;
    const int c0 = 2 * l, c1 = 2 * l + 1;

    // Stage the 136 tanh values into T.
    const float* rowp = ldata + (size_t)b * CHOL;
    for (int j = l; j < CHOL; j += 8) T[j] = rowp[j];
    __syncwarp();

    // Build columns c0,c1 of Q = L + L^T (tril idx(r,c) = r(r+1)/2 + c).
    float s0[16], s1[16];
    #pragma unroll
    for (int r = 0; r < 16; r++) {
        int hi0 = (r > c0) ? r : c0, lo0 = r + c0 - hi0;
        float v0 = T[hi0 * (hi0 + 1) / 2 + lo0];
        s0[r] = (r == c0) ? 2.f * v0 : v0;
        int hi1 = (r > c1) ? r : c1, lo1 = r + c1 - hi1;
        float v1 = T[hi1 * (hi1 + 1) / 2 + lo1];
        s1[r] = (r == c1) ? 2.f * v1 : v1;
    }
    __syncwarp();                       // done reading T
    #pragma unroll
    for (int r = 0; r < 16; r++)
        X2[r * 8 + l] = make_float2(s0[r], s1[r]);   // publish Q

    // Innermost Horner term: S = (2/3)I + (1/3)Q.
    #pragma unroll
    for (int r = 0; r < 16; r++) {
        s0[r] = s0[r] * (1.f / 3.f) + ((r == c0) ? (2.f / 3.f) : 0.f);
        s1[r] = s1[r] * (1.f / 3.f) + ((r == c1) ? (2.f / 3.f) : 0.f);
    }
    __syncwarp();                       // Q visible before matvec reads

    // Two middle rounds: S = I + Q*S.
    #pragma unroll 1
    for (int it = 0; it < 2; it++) {
        matvec2(X, s0, s1, T2, l);
        #pragma unroll
        for (int r = 0; r < 16; r++) {
            float2 t = T2[r * 8 + l];
            s0[r] = t.x + ((r == c0) ? 1.f : 0.f);
            s1[r] = t.y + ((r == c1) ? 1.f : 0.f);
        }
    }
    // Final: M = Q*S.
    matvec2(X, s0, s1, T2, l);
    #pragma unroll
    for (int r = 0; r < 16; r++) {
        float2 t = T2[r * 8 + l];
        s0[r] = t.x;
        s1[r] = t.y;
    }
    __syncwarp();                       // all X reads done
    #pragma unroll
    for (int r = 0; r < 16; r++)
        X2[r * 8 + l] = make_float2(s0[r], s1[r]);   // publish M

    // Ct = exp(M), degree-4 Horner: S = I + M/4, then k=3..1: S = I + (M/k)S.
    #pragma unroll
    for (int r = 0; r < 16; r++) {
        s0[r] = s0[r] * (1.f / NTERMS) + ((r == c0) ? 1.f : 0.f);
        s1[r] = s1[r] * (1.f / NTERMS) + ((r == c1) ? 1.f : 0.f);
    }
    __syncwarp();
    #pragma unroll 1
    for (int k = NTERMS - 1; k >= 1; k--) {
        matvec2(X, s0, s1, T2, l);
        float invk = c_invk[k];
        #pragma unroll
        for (int r = 0; r < 16; r++) {
            float2 t = T2[r * 8 + l];
            s0[r] = t.x * invk + ((r == c0) ? 1.f : 0.f);
            s1[r] = t.y * invk + ((r == c1) ? 1.f : 0.f);
        }
    }

    // scale = rsqrt(tr(Ct^2)) = rsqrt(sum_ij Ct_ij^2)  (Ct symmetric)
    float t = 0.f;
    #pragma unroll
    for (int r = 0; r < 16; r++) {
        t = fmaf(s0[r], s0[r], t);
        t = fmaf(s1[r], s1[r], t);
    }
    #pragma unroll
    for (int o = 4; o; o >>= 1) t += __shfl_xor_sync(FULLM, t, o);
    float scale = rsqrtf(t);

    float2* op2 = (float2*)(out + (size_t)b * 256);
    #pragma unroll
    for (int r = 0; r < 16; r++)
        op2[r * 8 + l] = make_float2(s0[r] * scale, s1[r] * scale);
}

// ---------------------------------------------------------------------------
extern "C" void kernel_launch(void* const* d_in, const int* in_sizes, int n_in,
                              void* d_out, int out_size)
{
    const float* x  = (const float*)d_in[0];
    const float* W1 = (const float*)d_in[1];
    const float* b1 = (const float*)d_in[2];
    const float* W2 = (const float*)d_in[3];
    const float* b2 = (const float*)d_in[4];
    const float* W3 = (const float*)d_in[5];
    const float* b3 = (const float*)d_in[6];
    float* out = (float*)d_out;

    float *h1, *h2, *ldp;
    cudaGetSymbolAddress((void**)&h1,  g_h1);
    cudaGetSymbolAddress((void**)&h2,  g_h2);
    cudaGetSymbolAddress((void**)&ldp, g_ld);

    dim3 blk(128);
    gemm_tf32<0><<<dim3(BATCH / 64, (HID  + 63) / 64), blk>>>(x,  W1, b1, h1,  BATCH, HID,  IN_DIM);
    gemm_tf32<0><<<dim3(BATCH / 64, (HID  + 63) / 64), blk>>>(h1, W2, b2, h2,  BATCH, HID,  HID);
    gemm_tf32<1><<<dim3(BATCH / 64, (CHOL + 63) / 64), blk>>>(h2, W3, b3, ldp, BATCH, CHOL, HID);
    psd_expm<<<BATCH / 16, 128>>>(ldp, out);
}

// round 13
// speedup vs baseline: 1.0340x; 1.0340x over previous
#include <cuda_runtime.h>
#include <math.h>
#include <stdint.h>

#define BATCH 65536
#define IN_DIM 64
#define HID 128
#define CHOL 136
#define FULLM 0xffffffffu

// Scratch
__device__ float g_h1[BATCH * HID];
__device__ float g_h2[BATCH * HID];
__device__ float g_ld[BATCH * CHOL];
// Pre-split weights (hi/lo tf32 parts)
__device__ float g_W1h[IN_DIM * HID],  g_W1l[IN_DIM * HID];
__device__ float g_W2h[HID * HID],     g_W2l[HID * HID];
__device__ float g_W3h[HID * CHOL],    g_W3l[HID * CHOL];

__device__ __forceinline__ void split_tf32(float v, float& hi, float& lo)
{
    uint32_t u = __float_as_uint(v) & 0xffffe000u;
    hi = __uint_as_float(u);
    float rem = v - hi;
    lo = __uint_as_float(__float_as_uint(rem) & 0xffffe000u);
}

__global__ void split_w_kernel(const float* __restrict__ W,
                               float* __restrict__ Wh, float* __restrict__ Wl,
                               int n)
{
    int i = blockIdx.x * 256 + threadIdx.x;
    if (i < n) {
        float h, l;
        split_tf32(W[i], h, l);
        Wh[i] = h;
        Wl[i] = l;
    }
}

// ---------------------------------------------------------------------------
// Tensor-core SGEMM via tf32 mma.sync, x3 precision split.
// B (weights) arrives PRE-SPLIT from gmem; A split hoisted per-k8 per warp.
//   C[M,N] = act(A[M,K] @ W[K,N] + b),  ACT: 0 = LeakyReLU(0.01), 1 = tanh.
// Block = 128 threads (4 warps), tile 64(M) x 64(N), K-chunk 16.
// Inner iteration (per nt): 4 LDS + 3 MMA.
// ---------------------------------------------------------------------------
__device__ __forceinline__ void mma_tf32(float* c, uint32_t a0, uint32_t a1,
                                         uint32_t a2, uint32_t a3,
                                         uint32_t b0, uint32_t b1)
{
    asm volatile(
        "mma.sync.aligned.m16n8k8.row.col.f32.tf32.tf32.f32 "
        "{%0,%1,%2,%3}, {%4,%5,%6,%7}, {%8,%9}, {%0,%1,%2,%3};\n"
        : "+f"(c[0]), "+f"(c[1]), "+f"(c[2]), "+f"(c[3])
        : "r"(a0), "r"(a1), "r"(a2), "r"(a3), "r"(b0), "r"(b1));
}

template<int ACT>
__global__ __launch_bounds__(128) void gemm_tf32(
    const float* __restrict__ A,
    const float* __restrict__ Wh, const float* __restrict__ Wl,
    const float* __restrict__ bias, float* __restrict__ C,
    int M, int N, int K)
{
    __shared__ float sA[64][20];                 // [m][k] raw fp32
    __shared__ float sWh[16][72], sWl[16][72];   // [k][n] hi/lo

    const int tid  = threadIdx.x;
    const int warp = tid >> 5, lane = tid & 31;
    const int grp  = lane >> 2, tig = lane & 3;
    const int bm   = blockIdx.x * 64, bn = blockIdx.y * 64;
    const int wrow = warp * 16;

    const int ntmax = min(8, (N - bn + 7) >> 3);

    float c[8][4];
    #pragma unroll
    for (int t = 0; t < 8; t++)
        #pragma unroll
        for (int j = 0; j < 4; j++) c[t][j] = 0.f;

    for (int k0 = 0; k0 < K; k0 += 16) {
        // Stage A 64x16 (2 float4 per thread).
        #pragma unroll
        for (int i = 0; i < 2; i++) {
            int idx = tid + i * 128;
            int row = idx >> 2, k4 = (idx & 3) * 4;
            float4 v = *(const float4*)&A[(size_t)(bm + row) * K + k0 + k4];
            *(float4*)&sA[row][k4] = v;
        }
        // Stage Wh/Wl 16x64 (2 float4 per thread each), zero-pad N tail.
        #pragma unroll
        for (int i = 0; i < 2; i++) {
            int idx = tid + i * 128;
            int kk = idx >> 4, c4 = (idx & 15) * 4;
            size_t base = (size_t)(k0 + kk) * N;
            int gc = bn + c4;
            float4 h, l;
            if (gc + 3 < N) {
                h = *(const float4*)&Wh[base + gc];
                l = *(const float4*)&Wl[base + gc];
            } else {
                h.x = (gc + 0 < N) ? Wh[base + gc + 0] : 0.f;
                h.y = (gc + 1 < N) ? Wh[base + gc + 1] : 0.f;
                h.z = (gc + 2 < N) ? Wh[base + gc + 2] : 0.f;
                h.w = (gc + 3 < N) ? Wh[base + gc + 3] : 0.f;
                l.x = (gc + 0 < N) ? Wl[base + gc + 0] : 0.f;
                l.y = (gc + 1 < N) ? Wl[base + gc + 1] : 0.f;
                l.z = (gc + 2 < N) ? Wl[base + gc + 2] : 0.f;
                l.w = (gc + 3 < N) ? Wl[base + gc + 3] : 0.f;
            }
            *(float4*)&sWh[kk][c4] = h;
            *(float4*)&sWl[kk][c4] = l;
        }
        __syncthreads();

        #pragma unroll
        for (int k8 = 0; k8 < 16; k8 += 8) {
            // A fragment + split (hoisted, amortized over 8 n-tiles).
            float av0 = sA[wrow + grp    ][k8 + tig    ];
            float av1 = sA[wrow + grp + 8][k8 + tig    ];
            float av2 = sA[wrow + grp    ][k8 + tig + 4];
            float av3 = sA[wrow + grp + 8][k8 + tig + 4];
            float h0, l0, h1, l1, h2, l2, h3, l3;
            split_tf32(av0, h0, l0);
            split_tf32(av1, h1, l1);
            split_tf32(av2, h2, l2);
            split_tf32(av3, h3, l3);
            uint32_t ah0 = __float_as_uint(h0), al0 = __float_as_uint(l0);
            uint32_t ah1 = __float_as_uint(h1), al1 = __float_as_uint(l1);
            uint32_t ah2 = __float_as_uint(h2), al2 = __float_as_uint(l2);
            uint32_t ah3 = __float_as_uint(h3), al3 = __float_as_uint(l3);

            for (int nt = 0; nt < ntmax; nt++) {
                uint32_t bh0 = __float_as_uint(sWh[k8 + tig    ][nt * 8 + grp]);
                uint32_t bh1 = __float_as_uint(sWh[k8 + tig + 4][nt * 8 + grp]);
                uint32_t bl0 = __float_as_uint(sWl[k8 + tig    ][nt * 8 + grp]);
                uint32_t bl1 = __float_as_uint(sWl[k8 + tig + 4][nt * 8 + grp]);

                mma_tf32(c[nt], ah0, ah1, ah2, ah3, bh0, bh1);
                mma_tf32(c[nt], ah0, ah1, ah2, ah3, bl0, bl1);
                mma_tf32(c[nt], al0, al1, al2, al3, bh0, bh1);
            }
        }
        __syncthreads();
    }

    // Epilogue: c[nt] regs -> rows (grp, grp+8), cols (2*tig, 2*tig+1).
    const int r0 = bm + wrow + grp;
    for (int nt = 0; nt < ntmax; nt++) {
        int col = bn + nt * 8 + 2 * tig;
        if (col >= N) continue;
        bool c2ok = (col + 1 < N);
        float b0v = bias[col];
        float b1v = c2ok ? bias[col + 1] : 0.f;
        #pragma unroll
        for (int h = 0; h < 2; h++) {
            float v0 = c[nt][2 * h + 0] + b0v;
            float v1 = c[nt][2 * h + 1] + b1v;
            if (ACT == 0) {
                v0 = (v0 > 0.f) ? v0 : 0.01f * v0;
                v1 = (v1 > 0.f) ? v1 : 0.01f * v1;
            } else {
                v0 = tanhf(v0); v1 = tanhf(v1);
            }
            float* cp = &C[(size_t)(r0 + 8 * h) * N + col];
            if (c2ok) { cp[0] = v0; cp[1] = v1; }
            else      { cp[0] = v0; }
        }
    }
}

// ---------------------------------------------------------------------------
// Eigendecomposition-free PSD head, fused polynomial form (R12, measured win):
//   out = Ct / sqrt(tr(Ct^2)),  Ct = exp(M),
//   M = (exp(2Q)-I)/2 ~= Q(I + Q(I + Q((2/3)I + (1/3)Q)))   [3 matvecs]
//   exp(M): degree-4 Taylor Horner                           [3 matvecs]
// ---------------------------------------------------------------------------
#define RST 16
#define MST 520
#define NTERMS 4

__constant__ float c_invk[NTERMS] = {0.f, 1.f, 0.5f, 1.f/3.f};

__device__ __forceinline__ void matvec2(const float* __restrict__ X,
                                        const float* __restrict__ s0,
                                        const float* __restrict__ s1,
                                        float2* __restrict__ T2, int l)
{
    #pragma unroll 1
    for (int r = 0; r < 16; r++) {
        const float4* row = (const float4*)(X + r * RST);
        float4 x0 = row[0], x1 = row[1], x2 = row[2], x3 = row[3];
        float a0 = x0.x * s0[0],  b0 = x0.y * s0[1];
        float a1 = x0.x * s1[0],  b1 = x0.y * s1[1];
        a0 = fmaf(x0.z, s0[2],  a0);  b0 = fmaf(x0.w, s0[3],  b0);
        a1 = fmaf(x0.z, s1[2],  a1);  b1 = fmaf(x0.w, s1[3],  b1);
        a0 = fmaf(x1.x, s0[4],  a0);  b0 = fmaf(x1.y, s0[5],  b0);
        a1 = fmaf(x1.x, s1[4],  a1);  b1 = fmaf(x1.y, s1[5],  b1);
        a0 = fmaf(x1.z, s0[6],  a0);  b0 = fmaf(x1.w, s0[7],  b0);
        a1 = fmaf(x1.z, s1[6],  a1);  b1 = fmaf(x1.w, s1[7],  b1);
        a0 = fmaf(x2.x, s0[8],  a0);  b0 = fmaf(x2.y, s0[9],  b0);
        a1 = fmaf(x2.x, s1[8],  a1);  b1 = fmaf(x2.y, s1[9],  b1);
        a0 = fmaf(x2.z, s0[10], a0);  b0 = fmaf(x2.w, s0[11], b0);
        a1 = fmaf(x2.z, s1[10], a1);  b1 = fmaf(x2.w, s1[11], b1);
        a0 = fmaf(x3.x, s0[12], a0);  b0 = fmaf(x3.y, s0[13], b0);
        a1 = fmaf(x3.x, s1[12], a1);  b1 = fmaf(x3.y, s1[13], b1);
        a0 = fmaf(x3.z, s0[14], a0);  b0 = fmaf(x3.w, s0[15], b0);
        a1 = fmaf(x3.z, s1[14], a1);  b1 = fmaf(x3.w, s1[15], b1);
        T2[r * 8 + l] = make_float2(a0 + b0, a1 + b1);
    }
}

__global__ __launch_bounds__(128, 6) void psd_expm(
    const float* __restrict__ ldata, float* __restrict__ out)
{
    __shared__ __align__(16) float sh[16 * MST];
    const int tid = threadIdx.x;
    const int g   = tid >> 3;
    const int l   = tid & 7;
    const int b   = blockIdx.x * 16 + g;
    float* X  = sh + g * MST;
    float* T  = X + 256;
    float2* X2 = (float2*)X;
    float2* T2 = (float2*)T;
    const int c0 = 2 * l, c1 = 2 * l + 1;

    const float* rowp = ldata + (size_t)b * CHOL;
    for (int j = l; j < CHOL; j += 8) T[j] = rowp[j];
    __syncwarp();

    float s0[16], s1[16];
    #pragma unroll
    for (int r = 0; r < 16; r++) {
        int hi0 = (r > c0) ? r : c0, lo0 = r + c0 - hi0;
        float v0 = T[hi0 * (hi0 + 1) / 2 + lo0];
        s0[r] = (r == c0) ? 2.f * v0 : v0;
        int hi1 = (r > c1) ? r : c1, lo1 = r + c1 - hi1;
        float v1 = T[hi1 * (hi1 + 1) / 2 + lo1];
        s1[r] = (r == c1) ? 2.f * v1 : v1;
    }
    __syncwarp();
    #pragma unroll
    for (int r = 0; r < 16; r++)
        X2[r * 8 + l] = make_float2(s0[r], s1[r]);   // publish Q

    #pragma unroll
    for (int r = 0; r < 16; r++) {
        s0[r] = s0[r] * (1.f / 3.f) + ((r == c0) ? (2.f / 3.f) : 0.f);
        s1[r] = s1[r] * (1.f / 3.f) + ((r == c1) ? (2.f / 3.f) : 0.f);
    }
    __syncwarp();

    #pragma unroll 1
    for (int it = 0; it < 2; it++) {
        matvec2(X, s0, s1, T2, l);
        #pragma unroll
        for (int r = 0; r < 16; r++) {
            float2 t = T2[r * 8 + l];
            s0[r] = t.x + ((r == c0) ? 1.f : 0.f);
            s1[r] = t.y + ((r == c1) ? 1.f : 0.f);
        }
    }
    matvec2(X, s0, s1, T2, l);
    #pragma unroll
    for (int r = 0; r < 16; r++) {
        float2 t = T2[r * 8 + l];
        s0[r] = t.x;
        s1[r] = t.y;
    }
    __syncwarp();
    #pragma unroll
    for (int r = 0; r < 16; r++)
        X2[r * 8 + l] = make_float2(s0[r], s1[r]);   // publish M

    #pragma unroll
    for (int r = 0; r < 16; r++) {
        s0[r] = s0[r] * (1.f / NTERMS) + ((r == c0) ? 1.f : 0.f);
        s1[r] = s1[r] * (1.f / NTERMS) + ((r == c1) ? 1.f : 0.f);
    }
    __syncwarp();
    #pragma unroll 1
    for (int k = NTERMS - 1; k >= 1; k--) {
        matvec2(X, s0, s1, T2, l);
        float invk = c_invk[k];
        #pragma unroll
        for (int r = 0; r < 16; r++) {
            float2 t = T2[r * 8 + l];
            s0[r] = t.x * invk + ((r == c0) ? 1.f : 0.f);
            s1[r] = t.y * invk + ((r == c1) ? 1.f : 0.f);
        }
    }

    float t = 0.f;
    #pragma unroll
    for (int r = 0; r < 16; r++) {
        t = fmaf(s0[r], s0[r], t);
        t = fmaf(s1[r], s1[r], t);
    }
    #pragma unroll
    for (int o = 4; o; o >>= 1) t += __shfl_xor_sync(FULLM, t, o);
    float scale = rsqrtf(t);

    float2* op2 = (float2*)(out + (size_t)b * 256);
    #pragma unroll
    for (int r = 0; r < 16; r++)
        op2[r * 8 + l] = make_float2(s0[r] * scale, s1[r] * scale);
}

// ---------------------------------------------------------------------------
extern "C" void kernel_launch(void* const* d_in, const int* in_sizes, int n_in,
                              void* d_out, int out_size)
{
    const float* x  = (const float*)d_in[0];
    const float* W1 = (const float*)d_in[1];
    const float* b1 = (const float*)d_in[2];
    const float* W2 = (const float*)d_in[3];
    const float* b2 = (const float*)d_in[4];
    const float* W3 = (const float*)d_in[5];
    const float* b3 = (const float*)d_in[6];
    float* out = (float*)d_out;

    float *h1, *h2, *ldp;
    float *w1h, *w1l, *w2h, *w2l, *w3h, *w3l;
    cudaGetSymbolAddress((void**)&h1,  g_h1);
    cudaGetSymbolAddress((void**)&h2,  g_h2);
    cudaGetSymbolAddress((void**)&ldp, g_ld);
    cudaGetSymbolAddress((void**)&w1h, g_W1h);
    cudaGetSymbolAddress((void**)&w1l, g_W1l);
    cudaGetSymbolAddress((void**)&w2h, g_W2h);
    cudaGetSymbolAddress((void**)&w2l, g_W2l);
    cudaGetSymbolAddress((void**)&w3h, g_W3h);
    cudaGetSymbolAddress((void**)&w3l, g_W3l);

    split_w_kernel<<<(IN_DIM * HID + 255) / 256, 256>>>(W1, w1h, w1l, IN_DIM * HID);
    split_w_kernel<<<(HID * HID   + 255) / 256, 256>>>(W2, w2h, w2l, HID * HID);
    split_w_kernel<<<(HID * CHOL  + 255) / 256, 256>>>(W3, w3h, w3l, HID * CHOL);

    dim3 blk(128);
    gemm_tf32<0><<<dim3(BATCH / 64, (HID  + 63) / 64), blk>>>(x,  w1h, w1l, b1, h1,  BATCH, HID,  IN_DIM);
    gemm_tf32<0><<<dim3(BATCH / 64, (HID  + 63) / 64), blk>>>(h1, w2h, w2l, b2, h2,  BATCH, HID,  HID);
    gemm_tf32<1><<<dim3(BATCH / 64, (CHOL + 63) / 64), blk>>>(h2, w3h, w3l, b3, ldp, BATCH, CHOL, HID);
    psd_expm<<<BATCH / 16, 128>>>(ldp, out);
}

// round 14
// speedup vs baseline: 1.1416x; 1.1041x over previous
#include <cuda_runtime.h>
#include <math.h>
#include <stdint.h>

#define BATCH 65536
#define IN_DIM 64
#define HID 128
#define CHOL 136
#define FULLM 0xffffffffu

// Scratch
__device__ float g_h1[BATCH * HID];
__device__ float g_h2[BATCH * HID];
__device__ float g_ld[BATCH * CHOL];
// Fragment-ordered pre-split weights: per (kb, nt, lane) -> (bh0,bh1,bl0,bl1)
__device__ float4 g_F1[(IN_DIM / 8) * 16 * 32];   // K=64,  N=128 (NT=16)
__device__ float4 g_F2[(HID / 8)    * 16 * 32];   // K=128, N=128 (NT=16)
__device__ float4 g_F3[(HID / 8)    * 17 * 32];   // K=128, N=136 (NT=17)

__device__ __forceinline__ void split_tf32(float v, float& hi, float& lo)
{
    uint32_t u = __float_as_uint(v) & 0xffffe000u;
    hi = __uint_as_float(u);
    float rem = v - hi;
    lo = __uint_as_float(__float_as_uint(rem) & 0xffffe000u);
}

// Build fragment-ordered, tf32-split W:  F[(kb*NT + nt)*32 + lane]
//   = (hi(W[kb*8+tig][nt*8+grp]), hi(W[kb*8+tig+4][...]), lo(..), lo(..))
__global__ void build_wfrag(const float* __restrict__ W, float4* __restrict__ F,
                            int K, int N, int NT)
{
    int idx = blockIdx.x * 256 + threadIdx.x;
    int total = (K / 8) * NT * 32;
    if (idx >= total) return;
    int lane = idx & 31;
    int nt = (idx >> 5) % NT;
    int kb = (idx >> 5) / NT;
    int grp = lane >> 2, tig = lane & 3;
    int col = nt * 8 + grp;
    float w0 = 0.f, w1 = 0.f;
    if (col < N) {
        w0 = W[(size_t)(kb * 8 + tig) * N + col];
        w1 = W[(size_t)(kb * 8 + tig + 4) * N + col];
    }
    float h0, l0, h1, l1;
    split_tf32(w0, h0, l0);
    split_tf32(w1, h1, l1);
    F[idx] = make_float4(h0, h1, l0, l1);
}

// ---------------------------------------------------------------------------
// Tensor-core SGEMM, tf32 mma.sync x3 split, fragment-ordered W from gmem.
// Block = 256 threads (8 warps), tile 128(M) x 64(N), K-chunk 16.
// Inner loop per n-tile: 1 LDS.128 + 3 MMA.
// ---------------------------------------------------------------------------
__device__ __forceinline__ void mma_tf32(float* c, uint32_t a0, uint32_t a1,
                                         uint32_t a2, uint32_t a3,
                                         uint32_t b0, uint32_t b1)
{
    asm volatile(
        "mma.sync.aligned.m16n8k8.row.col.f32.tf32.tf32.f32 "
        "{%0,%1,%2,%3}, {%4,%5,%6,%7}, {%8,%9}, {%0,%1,%2,%3};\n"
        : "+f"(c[0]), "+f"(c[1]), "+f"(c[2]), "+f"(c[3])
        : "r"(a0), "r"(a1), "r"(a2), "r"(a3), "r"(b0), "r"(b1));
}

template<int ACT>
__global__ __launch_bounds__(256) void gemm_tf32(
    const float* __restrict__ A, const float4* __restrict__ Fg,
    const float* __restrict__ bias, float* __restrict__ C,
    int M, int N, int K, int NT)
{
    __shared__ float sA[128][20];          // [m][k] raw fp32
    __shared__ float4 sF[2][8][32];        // [k8][nt][lane] W fragments

    const int tid  = threadIdx.x;
    const int warp = tid >> 5, lane = tid & 31;
    const int grp  = lane >> 2, tig = lane & 3;
    const int bm   = blockIdx.x * 128, bn = blockIdx.y * 64;
    const int bn8  = bn >> 3;
    const int wrow = warp * 16;
    const int ntblk = min(8, NT - bn8);    // n-tiles this block

    float c[8][4];
    #pragma unroll
    for (int t = 0; t < 8; t++)
        #pragma unroll
        for (int j = 0; j < 4; j++) c[t][j] = 0.f;

    for (int k0 = 0; k0 < K; k0 += 16) {
        const int kb0 = k0 >> 3;
        // Stage A 128x16 (2 float4 per thread).
        #pragma unroll
        for (int i = 0; i < 2; i++) {
            int idx = tid + i * 256;
            int row = idx >> 2, k4 = (idx & 3) * 4;
            float4 v = *(const float4*)&A[(size_t)(bm + row) * K + k0 + k4];
            *(float4*)&sA[row][k4] = v;
        }
        // Stage W fragments: up to 512 float4, coalesced.
        #pragma unroll
        for (int i = 0; i < 2; i++) {
            int idx = tid + i * 256;
            int kb8 = idx >> 8;
            int nt  = (idx >> 5) & 7;
            int ln  = idx & 31;
            if (nt < ntblk)
                sF[kb8][nt][ln] =
                    Fg[((size_t)(kb0 + kb8) * NT + bn8 + nt) * 32 + ln];
        }
        __syncthreads();

        #pragma unroll
        for (int k8 = 0; k8 < 2; k8++) {
            // A fragment + split (hoisted, amortized over n-tiles).
            float av0 = sA[wrow + grp    ][k8 * 8 + tig    ];
            float av1 = sA[wrow + grp + 8][k8 * 8 + tig    ];
            float av2 = sA[wrow + grp    ][k8 * 8 + tig + 4];
            float av3 = sA[wrow + grp + 8][k8 * 8 + tig + 4];
            float h0, l0, h1, l1, h2, l2, h3, l3;
            split_tf32(av0, h0, l0);
            split_tf32(av1, h1, l1);
            split_tf32(av2, h2, l2);
            split_tf32(av3, h3, l3);
            uint32_t ah0 = __float_as_uint(h0), al0 = __float_as_uint(l0);
            uint32_t ah1 = __float_as_uint(h1), al1 = __float_as_uint(l1);
            uint32_t ah2 = __float_as_uint(h2), al2 = __float_as_uint(l2);
            uint32_t ah3 = __float_as_uint(h3), al3 = __float_as_uint(l3);

            if (ntblk == 8) {
                #pragma unroll
                for (int nt = 0; nt < 8; nt++) {
                    float4 bf = sF[k8][nt][lane];
                    uint32_t bh0 = __float_as_uint(bf.x);
                    uint32_t bh1 = __float_as_uint(bf.y);
                    uint32_t bl0 = __float_as_uint(bf.z);
                    uint32_t bl1 = __float_as_uint(bf.w);
                    mma_tf32(c[nt], ah0, ah1, ah2, ah3, bh0, bh1);
                    mma_tf32(c[nt], ah0, ah1, ah2, ah3, bl0, bl1);
                    mma_tf32(c[nt], al0, al1, al2, al3, bh0, bh1);
                }
            } else {
                for (int nt = 0; nt < ntblk; nt++) {
                    float4 bf = sF[k8][nt][lane];
                    uint32_t bh0 = __float_as_uint(bf.x);
                    uint32_t bh1 = __float_as_uint(bf.y);
                    uint32_t bl0 = __float_as_uint(bf.z);
                    uint32_t bl1 = __float_as_uint(bf.w);
                    mma_tf32(c[nt], ah0, ah1, ah2, ah3, bh0, bh1);
                    mma_tf32(c[nt], ah0, ah1, ah2, ah3, bl0, bl1);
                    mma_tf32(c[nt], al0, al1, al2, al3, bh0, bh1);
                }
            }
        }
        __syncthreads();
    }

    // Epilogue: c[nt] -> rows (grp, grp+8) of warp's 16-row band,
    //           cols (2*tig, 2*tig+1) of n-tile nt.
    const int r0 = bm + wrow + grp;
    for (int nt = 0; nt < ntblk; nt++) {
        int col = bn + nt * 8 + 2 * tig;
        if (col >= N) continue;
        bool c2ok = (col + 1 < N);
        float b0v = bias[col];
        float b1v = c2ok ? bias[col + 1] : 0.f;
        #pragma unroll
        for (int h = 0; h < 2; h++) {
            float v0 = c[nt][2 * h + 0] + b0v;
            float v1 = c[nt][2 * h + 1] + b1v;
            if (ACT == 0) {
                v0 = (v0 > 0.f) ? v0 : 0.01f * v0;
                v1 = (v1 > 0.f) ? v1 : 0.01f * v1;
            } else {
                v0 = tanhf(v0); v1 = tanhf(v1);
            }
            float* cp = &C[(size_t)(r0 + 8 * h) * N + col];
            if (c2ok) { cp[0] = v0; cp[1] = v1; }
            else      { cp[0] = v0; }
        }
    }
}

// ---------------------------------------------------------------------------
// Eigendecomposition-free PSD head, fused polynomial form (R12, measured):
//   out = Ct / sqrt(tr(Ct^2)),  Ct = exp(M),
//   M = (exp(2Q)-I)/2 ~= Q(I + Q(I + Q((2/3)I + (1/3)Q)))   [3 matvecs]
//   exp(M): degree-4 Taylor Horner                           [3 matvecs]
// ---------------------------------------------------------------------------
#define RST 16
#define MST 520
#define NTERMS 4

__constant__ float c_invk[NTERMS] = {0.f, 1.f, 0.5f, 1.f/3.f};

__device__ __forceinline__ void matvec2(const float* __restrict__ X,
                                        const float* __restrict__ s0,
                                        const float* __restrict__ s1,
                                        float2* __restrict__ T2, int l)
{
    #pragma unroll 1
    for (int r = 0; r < 16; r++) {
        const float4* row = (const float4*)(X + r * RST);
        float4 x0 = row[0], x1 = row[1], x2 = row[2], x3 = row[3];
        float a0 = x0.x * s0[0],  b0 = x0.y * s0[1];
        float a1 = x0.x * s1[0],  b1 = x0.y * s1[1];
        a0 = fmaf(x0.z, s0[2],  a0);  b0 = fmaf(x0.w, s0[3],  b0);
        a1 = fmaf(x0.z, s1[2],  a1);  b1 = fmaf(x0.w, s1[3],  b1);
        a0 = fmaf(x1.x, s0[4],  a0);  b0 = fmaf(x1.y, s0[5],  b0);
        a1 = fmaf(x1.x, s1[4],  a1);  b1 = fmaf(x1.y, s1[5],  b1);
        a0 = fmaf(x1.z, s0[6],  a0);  b0 = fmaf(x1.w, s0[7],  b0);
        a1 = fmaf(x1.z, s1[6],  a1);  b1 = fmaf(x1.w, s1[7],  b1);
        a0 = fmaf(x2.x, s0[8],  a0);  b0 = fmaf(x2.y, s0[9],  b0);
        a1 = fmaf(x2.x, s1[8],  a1);  b1 = fmaf(x2.y, s1[9],  b1);
        a0 = fmaf(x2.z, s0[10], a0);  b0 = fmaf(x2.w, s0[11], b0);
        a1 = fmaf(x2.z, s1[10], a1);  b1 = fmaf(x2.w, s1[11], b1);
        a0 = fmaf(x3.x, s0[12], a0);  b0 = fmaf(x3.y, s0[13], b0);
        a1 = fmaf(x3.x, s1[12], a1);  b1 = fmaf(x3.y, s1[13], b1);
        a0 = fmaf(x3.z, s0[14], a0);  b0 = fmaf(x3.w, s0[15], b0);
        a1 = fmaf(x3.z, s1[14], a1);  b1 = fmaf(x3.w, s1[15], b1);
        T2[r * 8 + l] = make_float2(a0 + b0, a1 + b1);
    }
}

__global__ __launch_bounds__(128, 6) void psd_expm(
    const float* __restrict__ ldata, float* __restrict__ out)
{
    __shared__ __align__(16) float sh[16 * MST];
    const int tid = threadIdx.x;
    const int g   = tid >> 3;
    const int l   = tid & 7;
    const int b   = blockIdx.x * 16 + g;
    float* X  = sh + g * MST;
    float* T  = X + 256;
    float2* X2 = (float2*)X;
    float2* T2 = (float2*)T;
    const int c0 = 2 * l, c1 = 2 * l + 1;

    const float* rowp = ldata + (size_t)b * CHOL;
    for (int j = l; j < CHOL; j += 8) T[j] = rowp[j];
    __syncwarp();

    float s0[16], s1[16];
    #pragma unroll
    for (int r = 0; r < 16; r++) {
        int hi0 = (r > c0) ? r : c0, lo0 = r + c0 - hi0;
        float v0 = T[hi0 * (hi0 + 1) / 2 + lo0];
        s0[r] = (r == c0) ? 2.f * v0 : v0;
        int hi1 = (r > c1) ? r : c1, lo1 = r + c1 - hi1;
        float v1 = T[hi1 * (hi1 + 1) / 2 + lo1];
        s1[r] = (r == c1) ? 2.f * v1 : v1;
    }
    __syncwarp();
    #pragma unroll
    for (int r = 0; r < 16; r++)
        X2[r * 8 + l] = make_float2(s0[r], s1[r]);   // publish Q

    #pragma unroll
    for (int r = 0; r < 16; r++) {
        s0[r] = s0[r] * (1.f / 3.f) + ((r == c0) ? (2.f / 3.f) : 0.f);
        s1[r] = s1[r] * (1.f / 3.f) + ((r == c1) ? (2.f / 3.f) : 0.f);
    }
    __syncwarp();

    #pragma unroll 1
    for (int it = 0; it < 2; it++) {
        matvec2(X, s0, s1, T2, l);
        #pragma unroll
        for (int r = 0; r < 16; r++) {
            float2 t = T2[r * 8 + l];
            s0[r] = t.x + ((r == c0) ? 1.f : 0.f);
            s1[r] = t.y + ((r == c1) ? 1.f : 0.f);
        }
    }
    matvec2(X, s0, s1, T2, l);
    #pragma unroll
    for (int r = 0; r < 16; r++) {
        float2 t = T2[r * 8 + l];
        s0[r] = t.x;
        s1[r] = t.y;
    }
    __syncwarp();
    #pragma unroll
    for (int r = 0; r < 16; r++)
        X2[r * 8 + l] = make_float2(s0[r], s1[r]);   // publish M

    #pragma unroll
    for (int r = 0; r < 16; r++) {
        s0[r] = s0[r] * (1.f / NTERMS) + ((r == c0) ? 1.f : 0.f);
        s1[r] = s1[r] * (1.f / NTERMS) + ((r == c1) ? 1.f : 0.f);
    }
    __syncwarp();
    #pragma unroll 1
    for (int k = NTERMS - 1; k >= 1; k--) {
        matvec2(X, s0, s1, T2, l);
        float invk = c_invk[k];
        #pragma unroll
        for (int r = 0; r < 16; r++) {
            float2 t = T2[r * 8 + l];
            s0[r] = t.x * invk + ((r == c0) ? 1.f : 0.f);
            s1[r] = t.y * invk + ((r == c1) ? 1.f : 0.f);
        }
    }

    float t = 0.f;
    #pragma unroll
    for (int r = 0; r < 16; r++) {
        t = fmaf(s0[r], s0[r], t);
        t = fmaf(s1[r], s1[r], t);
    }
    #pragma unroll
    for (int o = 4; o; o >>= 1) t += __shfl_xor_sync(FULLM, t, o);
    float scale = rsqrtf(t);

    float2* op2 = (float2*)(out + (size_t)b * 256);
    #pragma unroll
    for (int r = 0; r < 16; r++)
        op2[r * 8 + l] = make_float2(s0[r] * scale, s1[r] * scale);
}

// ---------------------------------------------------------------------------
extern "C" void kernel_launch(void* const* d_in, const int* in_sizes, int n_in,
                              void* d_out, int out_size)
{
    const float* x  = (const float*)d_in[0];
    const float* W1 = (const float*)d_in[1];
    const float* b1 = (const float*)d_in[2];
    const float* W2 = (const float*)d_in[3];
    const float* b2 = (const float*)d_in[4];
    const float* W3 = (const float*)d_in[5];
    const float* b3 = (const float*)d_in[6];
    float* out = (float*)d_out;

    float *h1, *h2, *ldp;
    float4 *f1, *f2, *f3;
    cudaGetSymbolAddress((void**)&h1,  g_h1);
    cudaGetSymbolAddress((void**)&h2,  g_h2);
    cudaGetSymbolAddress((void**)&ldp, g_ld);
    cudaGetSymbolAddress((void**)&f1,  g_F1);
    cudaGetSymbolAddress((void**)&f2,  g_F2);
    cudaGetSymbolAddress((void**)&f3,  g_F3);

    build_wfrag<<<((IN_DIM/8)*16*32 + 255) / 256, 256>>>(W1, f1, IN_DIM, HID, 16);
    build_wfrag<<<((HID/8)*16*32   + 255) / 256, 256>>>(W2, f2, HID,    HID, 16);
    build_wfrag<<<((HID/8)*17*32   + 255) / 256, 256>>>(W3, f3, HID,   CHOL, 17);

    dim3 blk(256);
    gemm_tf32<0><<<dim3(BATCH / 128, 2), blk>>>(x,  f1, b1, h1,  BATCH, HID,  IN_DIM, 16);
    gemm_tf32<0><<<dim3(BATCH / 128, 2), blk>>>(h1, f2, b2, h2,  BATCH, HID,  HID,    16);
    gemm_tf32<1><<<dim3(BATCH / 128, 3), blk>>>(h2, f3, b3, ldp, BATCH, CHOL, HID,    17);
    psd_expm<<<BATCH / 16, 128>>>(ldp, out);
}

// round 15
// speedup vs baseline: 1.2496x; 1.0947x over previous
#include <cuda_runtime.h>
#include <math.h>
#include <stdint.h>

#define BATCH 65536
#define IN_DIM 64
#define HID 128
#define CHOL 136
#define FULLM 0xffffffffu

// Scratch
__device__ float g_h1[BATCH * HID];
__device__ float g_h2[BATCH * HID];
__device__ float g_ld[BATCH * CHOL];
// Fragment-ordered pre-split weights: per (kb, nt, lane) -> (bh0,bh1,bl0,bl1)
__device__ float4 g_F1[(IN_DIM / 8) * 16 * 32];
__device__ float4 g_F2[(HID / 8)    * 16 * 32];
__device__ float4 g_F3[(HID / 8)    * 17 * 32];

__device__ __forceinline__ void split_tf32(float v, float& hi, float& lo)
{
    uint32_t u = __float_as_uint(v) & 0xffffe000u;
    hi = __uint_as_float(u);
    float rem = v - hi;
    lo = __uint_as_float(__float_as_uint(rem) & 0xffffe000u);
}

__global__ void build_wfrag(const float* __restrict__ W, float4* __restrict__ F,
                            int K, int N, int NT)
{
    int idx = blockIdx.x * 256 + threadIdx.x;
    int total = (K / 8) * NT * 32;
    if (idx >= total) return;
    int lane = idx & 31;
    int nt = (idx >> 5) % NT;
    int kb = (idx >> 5) / NT;
    int grp = lane >> 2, tig = lane & 3;
    int col = nt * 8 + grp;
    float w0 = 0.f, w1 = 0.f;
    if (col < N) {
        w0 = W[(size_t)(kb * 8 + tig) * N + col];
        w1 = W[(size_t)(kb * 8 + tig + 4) * N + col];
    }
    float h0, l0, h1, l1;
    split_tf32(w0, h0, l0);
    split_tf32(w1, h1, l1);
    F[idx] = make_float4(h0, h1, l0, l1);
}

// ---------------------------------------------------------------------------
// cp.async helpers
// ---------------------------------------------------------------------------
__device__ __forceinline__ void cp16(uint32_t dst, const void* src) {
    asm volatile("cp.async.ca.shared.global [%0], [%1], 16;\n" :: "r"(dst), "l"(src));
}
#define CP_COMMIT asm volatile("cp.async.commit_group;\n" ::: "memory")
#define CP_WAIT1  asm volatile("cp.async.wait_group 1;\n" ::: "memory")

// ---------------------------------------------------------------------------
// Tensor-core SGEMM, tf32 mma.sync x3 split, fragment-ordered W,
// cp.async double-buffered staging (gmem latency off the critical path).
// Block = 256 threads (8 warps), tile 128(M) x 64(N), K-chunk 16.
// ---------------------------------------------------------------------------
__device__ __forceinline__ void mma_tf32(float* c, uint32_t a0, uint32_t a1,
                                         uint32_t a2, uint32_t a3,
                                         uint32_t b0, uint32_t b1)
{
    asm volatile(
        "mma.sync.aligned.m16n8k8.row.col.f32.tf32.tf32.f32 "
        "{%0,%1,%2,%3}, {%4,%5,%6,%7}, {%8,%9}, {%0,%1,%2,%3};\n"
        : "+f"(c[0]), "+f"(c[1]), "+f"(c[2]), "+f"(c[3])
        : "r"(a0), "r"(a1), "r"(a2), "r"(a3), "r"(b0), "r"(b1));
}

template<int ACT>
__global__ __launch_bounds__(256) void gemm_tf32(
    const float* __restrict__ A, const float4* __restrict__ Fg,
    const float* __restrict__ bias, float* __restrict__ C,
    int M, int N, int K, int NT)
{
    __shared__ float  sA[2][128][20];
    __shared__ float4 sF[2][2][8][32];

    const int tid  = threadIdx.x;
    const int warp = tid >> 5, lane = tid & 31;
    const int grp  = lane >> 2, tig = lane & 3;
    const int bm   = blockIdx.x * 128, bn = blockIdx.y * 64;
    const int bn8  = bn >> 3;
    const int wrow = warp * 16;
    const int ntblk = min(8, NT - bn8);

    // Per-thread staging coordinates (tile-invariant).
    const int a_row0 = tid >> 2,        a_k4 = (tid & 3) * 4;        // + i*64 rows
    const int f_kb8_0 = tid >> 8;       // 0 for i=0, 1 for i=1 handled below
    float c[8][4];
    #pragma unroll
    for (int t = 0; t < 8; t++)
        #pragma unroll
        for (int j = 0; j < 4; j++) c[t][j] = 0.f;

    const int nk = K >> 4;

    // Prefetch macro: tile kt -> buffer p.
    #define PREFETCH(KT, P)                                                    \
    do {                                                                       \
        int k0_ = (KT) << 4;                                                   \
        _Pragma("unroll")                                                      \
        for (int i = 0; i < 2; i++) {                                          \
            int row = a_row0 + i * 64;                                         \
            uint32_t d = (uint32_t)__cvta_generic_to_shared(&sA[P][row][a_k4]);\
            cp16(d, &A[(size_t)(bm + row) * K + k0_ + a_k4]);                  \
        }                                                                      \
        _Pragma("unroll")                                                      \
        for (int i = 0; i < 2; i++) {                                          \
            int idx = tid + i * 256;                                           \
            int kb8 = idx >> 8, nt = (idx >> 5) & 7, ln = idx & 31;            \
            if (nt < ntblk) {                                                  \
                uint32_t d = (uint32_t)__cvta_generic_to_shared(&sF[P][kb8][nt][ln]); \
                cp16(d, &Fg[((size_t)((k0_ >> 3) + kb8) * NT + bn8 + nt) * 32 + ln]); \
            }                                                                  \
        }                                                                      \
    } while (0)

    PREFETCH(0, 0);
    CP_COMMIT;

    for (int kt = 0; kt < nk; kt++) {
        const int p = kt & 1;
        if (kt + 1 < nk) PREFETCH(kt + 1, (kt + 1) & 1);
        CP_COMMIT;
        CP_WAIT1;
        __syncthreads();

        #pragma unroll
        for (int k8 = 0; k8 < 2; k8++) {
            float av0 = sA[p][wrow + grp    ][k8 * 8 + tig    ];
            float av1 = sA[p][wrow + grp + 8][k8 * 8 + tig    ];
            float av2 = sA[p][wrow + grp    ][k8 * 8 + tig + 4];
            float av3 = sA[p][wrow + grp + 8][k8 * 8 + tig + 4];
            float h0, l0, h1, l1, h2, l2, h3, l3;
            split_tf32(av0, h0, l0);
            split_tf32(av1, h1, l1);
            split_tf32(av2, h2, l2);
            split_tf32(av3, h3, l3);
            uint32_t ah0 = __float_as_uint(h0), al0 = __float_as_uint(l0);
            uint32_t ah1 = __float_as_uint(h1), al1 = __float_as_uint(l1);
            uint32_t ah2 = __float_as_uint(h2), al2 = __float_as_uint(l2);
            uint32_t ah3 = __float_as_uint(h3), al3 = __float_as_uint(l3);

            if (ntblk == 8) {
                #pragma unroll
                for (int nt = 0; nt < 8; nt++) {
                    float4 bf = sF[p][k8][nt][lane];
                    mma_tf32(c[nt], ah0, ah1, ah2, ah3,
                             __float_as_uint(bf.x), __float_as_uint(bf.y));
                    mma_tf32(c[nt], ah0, ah1, ah2, ah3,
                             __float_as_uint(bf.z), __float_as_uint(bf.w));
                    mma_tf32(c[nt], al0, al1, al2, al3,
                             __float_as_uint(bf.x), __float_as_uint(bf.y));
                }
            } else {
                for (int nt = 0; nt < ntblk; nt++) {
                    float4 bf = sF[p][k8][nt][lane];
                    mma_tf32(c[nt], ah0, ah1, ah2, ah3,
                             __float_as_uint(bf.x), __float_as_uint(bf.y));
                    mma_tf32(c[nt], ah0, ah1, ah2, ah3,
                             __float_as_uint(bf.z), __float_as_uint(bf.w));
                    mma_tf32(c[nt], al0, al1, al2, al3,
                             __float_as_uint(bf.x), __float_as_uint(bf.y));
                }
            }
        }
        __syncthreads();
    }
    #undef PREFETCH

    // Epilogue
    const int r0 = bm + wrow + grp;
    for (int nt = 0; nt < ntblk; nt++) {
        int col = bn + nt * 8 + 2 * tig;
        if (col >= N) continue;
        bool c2ok = (col + 1 < N);
        float b0v = bias[col];
        float b1v = c2ok ? bias[col + 1] : 0.f;
        #pragma unroll
        for (int h = 0; h < 2; h++) {
            float v0 = c[nt][2 * h + 0] + b0v;
            float v1 = c[nt][2 * h + 1] + b1v;
            if (ACT == 0) {
                v0 = (v0 > 0.f) ? v0 : 0.01f * v0;
                v1 = (v1 > 0.f) ? v1 : 0.01f * v1;
            } else {
                v0 = tanhf(v0); v1 = tanhf(v1);
            }
            float* cp = &C[(size_t)(r0 + 8 * h) * N + col];
            if (c2ok) { cp[0] = v0; cp[1] = v1; }
            else      { cp[0] = v0; }
        }
    }
}

// ---------------------------------------------------------------------------
// PSD head, Paterson-Stockmeyer (4 matvecs):
//   M  = Q + Q2·(I + (2/3)Q + (1/3)Q2),  Q2 = Q·Q
//   Ct = I + M + M2·(I/2 + M/6 + M2/24), M2 = M·M
//   out = Ct / sqrt(tr(Ct^2))
// 8 lanes/matrix, 2 cols/lane.  X, T are [16 rows][16 cols] smem buffers.
// All vector fusions read/write the lane's OWN column (no cross-lane races,
// no runtime-indexed register arrays).
// ---------------------------------------------------------------------------
#define RST 16
#define MST 520

__device__ __forceinline__ void mv_core(const float* __restrict__ S,
                                        const float* __restrict__ s0,
                                        const float* __restrict__ s1,
                                        float& a, float& b, int r)
{
    const float4* row = (const float4*)(S + r * RST);
    float4 x0 = row[0], x1 = row[1], x2 = row[2], x3 = row[3];
    float a0 = x0.x * s0[0],  b0 = x0.y * s0[1];
    float a1 = x0.x * s1[0],  b1 = x0.y * s1[1];
    a0 = fmaf(x0.z, s0[2],  a0);  b0 = fmaf(x0.w, s0[3],  b0);
    a1 = fmaf(x0.z, s1[2],  a1);  b1 = fmaf(x0.w, s1[3],  b1);
    a0 = fmaf(x1.x, s0[4],  a0);  b0 = fmaf(x1.y, s0[5],  b0);
    a1 = fmaf(x1.x, s1[4],  a1);  b1 = fmaf(x1.y, s1[5],  b1);
    a0 = fmaf(x1.z, s0[6],  a0);  b0 = fmaf(x1.w, s0[7],  b0);
    a1 = fmaf(x1.z, s1[6],  a1);  b1 = fmaf(x1.w, s1[7],  b1);
    a0 = fmaf(x2.x, s0[8],  a0);  b0 = fmaf(x2.y, s0[9],  b0);
    a1 = fmaf(x2.x, s1[8],  a1);  b1 = fmaf(x2.y, s1[9],  b1);
    a0 = fmaf(x2.z, s0[10], a0);  b0 = fmaf(x2.w, s0[11], b0);
    a1 = fmaf(x2.z, s1[10], a1);  b1 = fmaf(x2.w, s1[11], b1);
    a0 = fmaf(x3.x, s0[12], a0);  b0 = fmaf(x3.y, s0[13], b0);
    a1 = fmaf(x3.x, s1[12], a1);  b1 = fmaf(x3.y, s1[13], b1);
    a0 = fmaf(x3.z, s0[14], a0);  b0 = fmaf(x3.w, s0[15], b0);
    a1 = fmaf(x3.z, s1[14], a1);  b1 = fmaf(x3.w, s1[15], b1);
    a = a0 + b0;
    b = a1 + b1;
}

// D = S·s  (plain)
__device__ __forceinline__ void mv_plain(const float* __restrict__ S,
                                         const float* __restrict__ s0,
                                         const float* __restrict__ s1,
                                         float2* __restrict__ D2, int l)
{
    #pragma unroll 1
    for (int r = 0; r < 16; r++) {
        float a, b;
        mv_core(S, s0, s1, a, b, r);
        D2[r * 8 + l] = make_float2(a, b);
    }
}

// D(own col) += S·s  (fused add of D's prior own-column value)
__device__ __forceinline__ void mv_addcol(const float* __restrict__ S,
                                          const float* __restrict__ s0,
                                          const float* __restrict__ s1,
                                          float2* __restrict__ D2, int l)
{
    #pragma unroll 1
    for (int r = 0; r < 16; r++) {
        float a, b;
        mv_core(S, s0, s1, a, b, r);
        float2 q = D2[r * 8 + l];
        D2[r * 8 + l] = make_float2(q.x + a, q.y + b);
    }
}

// ct = e + X(own col, =M) + S·s ; write ct to X own col; return sum(ct^2)
__device__ __forceinline__ float mv_final(const float* __restrict__ S,
                                          const float* __restrict__ s0,
                                          const float* __restrict__ s1,
                                          float2* X2, int l, int c0, int c1)
{
    float tr = 0.f;
    #pragma unroll 1
    for (int r = 0; r < 16; r++) {
        float a, b;
        mv_core(S, s0, s1, a, b, r);
        float2 m = X2[r * 8 + l];
        float ct0 = ((r == c0) ? 1.f : 0.f) + m.x + a;
        float ct1 = ((r == c1) ? 1.f : 0.f) + m.y + b;
        X2[r * 8 + l] = make_float2(ct0, ct1);
        tr = fmaf(ct0, ct0, tr);
        tr = fmaf(ct1, ct1, tr);
    }
    return tr;
}

__global__ __launch_bounds__(128, 6) void psd_expm(
    const float* __restrict__ ldata, float* __restrict__ out)
{
    __shared__ __align__(16) float sh[16 * MST];
    const int tid = threadIdx.x;
    const int g   = tid >> 3;
    const int l   = tid & 7;
    const int b   = blockIdx.x * 16 + g;
    float* X  = sh + g * MST;
    float* T  = X + 256;
    float2* X2 = (float2*)X;
    float2* T2 = (float2*)T;
    const int c0 = 2 * l, c1 = 2 * l + 1;

    // Stage 136 tanh values into T.
    const float* rowp = ldata + (size_t)b * CHOL;
    for (int j = l; j < CHOL; j += 8) T[j] = rowp[j];
    __syncwarp();

    // q cols of Q = L + L^T.
    float y0[16], y1[16];
    #pragma unroll
    for (int r = 0; r < 16; r++) {
        int hi0 = (r > c0) ? r : c0, lo0 = r + c0 - hi0;
        float v0 = T[hi0 * (hi0 + 1) / 2 + lo0];
        y0[r] = (r == c0) ? 2.f * v0 : v0;
        int hi1 = (r > c1) ? r : c1, lo1 = r + c1 - hi1;
        float v1 = T[hi1 * (hi1 + 1) / 2 + lo1];
        y1[r] = (r == c1) ? 2.f * v1 : v1;
    }
    __syncwarp();                        // T reads done (mv1 writes T next)
    #pragma unroll
    for (int r = 0; r < 16; r++)
        X2[r * 8 + l] = make_float2(y0[r], y1[r]);   // publish Q
    __syncwarp();

    // mv1: T = Q·q  (cols of Q2)
    mv_plain(X, y0, y1, T2, l);
    // y = e + (2/3)q + (1/3)q2  (own col of T, no sync needed)
    #pragma unroll
    for (int r = 0; r < 16; r++) {
        float2 t = T2[r * 8 + l];
        y0[r] = ((r == c0) ? 1.f : 0.f) + (2.f / 3.f) * y0[r] + (1.f / 3.f) * t.x;
        y1[r] = ((r == c1) ? 1.f : 0.f) + (2.f / 3.f) * y1[r] + (1.f / 3.f) * t.y;
    }
    __syncwarp();                        // Q2 fully in T for cross-lane reads

    // mv2: X = Q(own col) + Q2·y   -> X holds M
    mv_addcol(T, y0, y1, X2, l);
    // m = own col of X
    #pragma unroll
    for (int r = 0; r < 16; r++) {
        float2 t = X2[r * 8 + l];
        y0[r] = t.x;
        y1[r] = t.y;
    }
    __syncwarp();                        // M fully in X

    // mv3: T = M·m  (cols of M2)
    mv_plain(X, y0, y1, T2, l);
    // z = e/2 + m/6 + m2/24
    #pragma unroll
    for (int r = 0; r < 16; r++) {
        float2 t = T2[r * 8 + l];
        y0[r] = ((r == c0) ? 0.5f : 0.f) + (1.f / 6.f) * y0[r] + (1.f / 24.f) * t.x;
        y1[r] = ((r == c1) ? 0.5f : 0.f) + (1.f / 6.f) * y1[r] + (1.f / 24.f) * t.y;
    }
    __syncwarp();                        // M2 fully in T

    // mv4: ct = e + m + M2·z ; trace accumulated inline
    float tr = mv_final(T, y0, y1, X2, l, c0, c1);
    #pragma unroll
    for (int o = 4; o; o >>= 1) tr += __shfl_xor_sync(FULLM, tr, o);
    float scale = rsqrtf(tr);

    float2* op2 = (float2*)(out + (size_t)b * 256);
    #pragma unroll
    for (int r = 0; r < 16; r++) {
        float2 ct = X2[r * 8 + l];
        op2[r * 8 + l] = make_float2(ct.x * scale, ct.y * scale);
    }
}

// ---------------------------------------------------------------------------
extern "C" void kernel_launch(void* const* d_in, const int* in_sizes, int n_in,
                              void* d_out, int out_size)
{
    const float* x  = (const float*)d_in[0];
    const float* W1 = (const float*)d_in[1];
    const float* b1 = (const float*)d_in[2];
    const float* W2 = (const float*)d_in[3];
    const float* b2 = (const float*)d_in[4];
    const float* W3 = (const float*)d_in[5];
    const float* b3 = (const float*)d_in[6];
    float* out = (float*)d_out;

    float *h1, *h2, *ldp;
    float4 *f1, *f2, *f3;
    cudaGetSymbolAddress((void**)&h1,  g_h1);
    cudaGetSymbolAddress((void**)&h2,  g_h2);
    cudaGetSymbolAddress((void**)&ldp, g_ld);
    cudaGetSymbolAddress((void**)&f1,  g_F1);
    cudaGetSymbolAddress((void**)&f2,  g_F2);
    cudaGetSymbolAddress((void**)&f3,  g_F3);

    build_wfrag<<<((IN_DIM/8)*16*32 + 255) / 256, 256>>>(W1, f1, IN_DIM, HID, 16);
    build_wfrag<<<((HID/8)*16*32   + 255) / 256, 256>>>(W2, f2, HID,    HID, 16);
    build_wfrag<<<((HID/8)*17*32   + 255) / 256, 256>>>(W3, f3, HID,   CHOL, 17);

    dim3 blk(256);
    gemm_tf32<0><<<dim3(BATCH / 128, 2), blk>>>(x,  f1, b1, h1,  BATCH, HID,  IN_DIM, 16);
    gemm_tf32<0><<<dim3(BATCH / 128, 2), blk>>>(h1, f2, b2, h2,  BATCH, HID,  HID,    16);
    gemm_tf32<1><<<dim3(BATCH / 128, 3), blk>>>(h2, f3, b3, ldp, BATCH, CHOL, HID,    17);
    psd_expm<<<BATCH / 16, 128>>>(ldp, out);
}

// round 16
// speedup vs baseline: 1.6228x; 1.2987x over previous
#include <cuda_runtime.h>
#include <math.h>
#include <stdint.h>

#define BATCH 65536
#define IN_DIM 64
#define HID 128
#define CHOL 136
#define FULLM 0xffffffffu

// Scratch
__device__ float g_h1[BATCH * HID];
__device__ float g_h2[BATCH * HID];
__device__ float g_ld[BATCH * CHOL];
// Fragment-ordered tf32 weights: per (kb, nt, lane) -> (b0, b1)
__device__ float2 g_F1[(IN_DIM / 8) * 16 * 32];
__device__ float2 g_F2[(HID / 8)    * 16 * 32];
__device__ float2 g_F3[(HID / 8)    * 17 * 32];

__device__ __forceinline__ uint32_t to_tf32(float v)
{
    uint32_t r;
    asm("cvt.rna.tf32.f32 %0, %1;" : "=r"(r) : "f"(v));
    return r;
}

__global__ void build_wfrag(const float* __restrict__ W, float2* __restrict__ F,
                            int K, int N, int NT)
{
    int idx = blockIdx.x * 256 + threadIdx.x;
    int total = (K / 8) * NT * 32;
    if (idx >= total) return;
    int lane = idx & 31;
    int nt = (idx >> 5) % NT;
    int kb = (idx >> 5) / NT;
    int grp = lane >> 2, tig = lane & 3;
    int col = nt * 8 + grp;
    float w0 = 0.f, w1 = 0.f;
    if (col < N) {
        w0 = W[(size_t)(kb * 8 + tig) * N + col];
        w1 = W[(size_t)(kb * 8 + tig + 4) * N + col];
    }
    F[idx] = make_float2(__uint_as_float(to_tf32(w0)),
                         __uint_as_float(to_tf32(w1)));
}

// ---------------------------------------------------------------------------
// cp.async helpers
// ---------------------------------------------------------------------------
__device__ __forceinline__ void cp16(uint32_t dst, const void* src) {
    asm volatile("cp.async.ca.shared.global [%0], [%1], 16;\n" :: "r"(dst), "l"(src));
}
#define CP_COMMIT asm volatile("cp.async.commit_group;\n" ::: "memory")
#define CP_WAIT1  asm volatile("cp.async.wait_group 1;\n" ::: "memory")

// ---------------------------------------------------------------------------
// Tensor-core SGEMM, raw tf32 mma.sync (single MMA per 8x8 n-tile per k8),
// fragment-ordered pre-converted W, cp.async double-buffered staging.
// Block = 256 threads (8 warps), tile 128(M) x 64(N), K-chunk 16.
// ---------------------------------------------------------------------------
__device__ __forceinline__ void mma_tf32(float* c, uint32_t a0, uint32_t a1,
                                         uint32_t a2, uint32_t a3,
                                         uint32_t b0, uint32_t b1)
{
    asm volatile(
        "mma.sync.aligned.m16n8k8.row.col.f32.tf32.tf32.f32 "
        "{%0,%1,%2,%3}, {%4,%5,%6,%7}, {%8,%9}, {%0,%1,%2,%3};\n"
        : "+f"(c[0]), "+f"(c[1]), "+f"(c[2]), "+f"(c[3])
        : "r"(a0), "r"(a1), "r"(a2), "r"(a3), "r"(b0), "r"(b1));
}

template<int ACT>
__global__ __launch_bounds__(256) void gemm_tf32(
    const float* __restrict__ A, const float2* __restrict__ Fg,
    const float* __restrict__ bias, float* __restrict__ C,
    int M, int N, int K, int NT)
{
    __shared__ float  sA[2][128][20];       // 20 KB
    __shared__ float2 sF[2][2][8][32];      // 8 KB

    const int tid  = threadIdx.x;
    const int warp = tid >> 5, lane = tid & 31;
    const int grp  = lane >> 2, tig = lane & 3;
    const int bm   = blockIdx.x * 128, bn = blockIdx.y * 64;
    const int bn8  = bn >> 3;
    const int wrow = warp * 16;
    const int ntblk = min(8, NT - bn8);

    const int a_row0 = tid >> 2, a_k4 = (tid & 3) * 4;

    float c[8][4];
    #pragma unroll
    for (int t = 0; t < 8; t++)
        #pragma unroll
        for (int j = 0; j < 4; j++) c[t][j] = 0.f;

    const int nk = K >> 4;

    #define PREFETCH(KT, P)                                                    \
    do {                                                                       \
        int k0_ = (KT) << 4;                                                   \
        _Pragma("unroll")                                                      \
        for (int i = 0; i < 2; i++) {                                          \
            int row = a_row0 + i * 64;                                         \
            uint32_t d = (uint32_t)__cvta_generic_to_shared(&sA[P][row][a_k4]);\
            cp16(d, &A[(size_t)(bm + row) * K + k0_ + a_k4]);                  \
        }                                                                      \
        {                                                                      \
            int kb8 = tid >> 7, t = tid & 127;                                 \
            if (t < ntblk * 16) {                                              \
                uint32_t d = (uint32_t)__cvta_generic_to_shared(               \
                    (float4*)&sF[P][kb8][0][0] + t);                           \
                cp16(d, (const float4*)(Fg +                                   \
                    ((size_t)((k0_ >> 3) + kb8) * NT + bn8) * 32) + t);        \
            }                                                                  \
        }                                                                      \
    } while (0)

    PREFETCH(0, 0);
    CP_COMMIT;

    for (int kt = 0; kt < nk; kt++) {
        const int p = kt & 1;
        if (kt + 1 < nk) PREFETCH(kt + 1, (kt + 1) & 1);
        CP_COMMIT;
        CP_WAIT1;
        __syncthreads();

        #pragma unroll
        for (int k8 = 0; k8 < 2; k8++) {
            uint32_t a0 = to_tf32(sA[p][wrow + grp    ][k8 * 8 + tig    ]);
            uint32_t a1 = to_tf32(sA[p][wrow + grp + 8][k8 * 8 + tig    ]);
            uint32_t a2 = to_tf32(sA[p][wrow + grp    ][k8 * 8 + tig + 4]);
            uint32_t a3 = to_tf32(sA[p][wrow + grp + 8][k8 * 8 + tig + 4]);

            if (ntblk == 8) {
                #pragma unroll
                for (int nt = 0; nt < 8; nt++) {
                    float2 bf = sF[p][k8][nt][lane];
                    mma_tf32(c[nt], a0, a1, a2, a3,
                             __float_as_uint(bf.x), __float_as_uint(bf.y));
                }
            } else {
                for (int nt = 0; nt < ntblk; nt++) {
                    float2 bf = sF[p][k8][nt][lane];
                    mma_tf32(c[nt], a0, a1, a2, a3,
                             __float_as_uint(bf.x), __float_as_uint(bf.y));
                }
            }
        }
        __syncthreads();
    }
    #undef PREFETCH

    // Epilogue: c[nt] -> rows (grp, grp+8), cols (2*tig, 2*tig+1).
    const int r0 = bm + wrow + grp;
    for (int nt = 0; nt < ntblk; nt++) {
        int col = bn + nt * 8 + 2 * tig;
        if (col >= N) continue;
        bool c2ok = (col + 1 < N);
        float b0v = bias[col];
        float b1v = c2ok ? bias[col + 1] : 0.f;
        #pragma unroll
        for (int h = 0; h < 2; h++) {
            float v0 = c[nt][2 * h + 0] + b0v;
            float v1 = c[nt][2 * h + 1] + b1v;
            if (ACT == 0) {
                v0 = (v0 > 0.f) ? v0 : 0.01f * v0;
                v1 = (v1 > 0.f) ? v1 : 0.01f * v1;
            } else {
                v0 = tanhf(v0); v1 = tanhf(v1);
            }
            float* cp = &C[(size_t)(r0 + 8 * h) * N + col];
            if (c2ok) { cp[0] = v0; cp[1] = v1; }
            else      { cp[0] = v0; }
        }
    }
}

// ---------------------------------------------------------------------------
// PSD head, Paterson-Stockmeyer (4 matvecs) — unchanged from R15 (measured):
//   M  = Q + Q2·(I + (2/3)Q + (1/3)Q2),  Q2 = Q·Q
//   Ct = I + M + M2·(I/2 + M/6 + M2/24), M2 = M·M
//   out = Ct / sqrt(tr(Ct^2))
// ---------------------------------------------------------------------------
#define RST 16
#define MST 520

__device__ __forceinline__ void mv_core(const float* __restrict__ S,
                                        const float* __restrict__ s0,
                                        const float* __restrict__ s1,
                                        float& a, float& b, int r)
{
    const float4* row = (const float4*)(S + r * RST);
    float4 x0 = row[0], x1 = row[1], x2 = row[2], x3 = row[3];
    float a0 = x0.x * s0[0],  b0 = x0.y * s0[1];
    float a1 = x0.x * s1[0],  b1 = x0.y * s1[1];
    a0 = fmaf(x0.z, s0[2],  a0);  b0 = fmaf(x0.w, s0[3],  b0);
    a1 = fmaf(x0.z, s1[2],  a1);  b1 = fmaf(x0.w, s1[3],  b1);
    a0 = fmaf(x1.x, s0[4],  a0);  b0 = fmaf(x1.y, s0[5],  b0);
    a1 = fmaf(x1.x, s1[4],  a1);  b1 = fmaf(x1.y, s1[5],  b1);
    a0 = fmaf(x1.z, s0[6],  a0);  b0 = fmaf(x1.w, s0[7],  b0);
    a1 = fmaf(x1.z, s1[6],  a1);  b1 = fmaf(x1.w, s1[7],  b1);
    a0 = fmaf(x2.x, s0[8],  a0);  b0 = fmaf(x2.y, s0[9],  b0);
    a1 = fmaf(x2.x, s1[8],  a1);  b1 = fmaf(x2.y, s1[9],  b1);
    a0 = fmaf(x2.z, s0[10], a0);  b0 = fmaf(x2.w, s0[11], b0);
    a1 = fmaf(x2.z, s1[10], a1);  b1 = fmaf(x2.w, s1[11], b1);
    a0 = fmaf(x3.x, s0[12], a0);  b0 = fmaf(x3.y, s0[13], b0);
    a1 = fmaf(x3.x, s1[12], a1);  b1 = fmaf(x3.y, s1[13], b1);
    a0 = fmaf(x3.z, s0[14], a0);  b0 = fmaf(x3.w, s0[15], b0);
    a1 = fmaf(x3.z, s1[14], a1);  b1 = fmaf(x3.w, s1[15], b1);
    a = a0 + b0;
    b = a1 + b1;
}

__device__ __forceinline__ void mv_plain(const float* __restrict__ S,
                                         const float* __restrict__ s0,
                                         const float* __restrict__ s1,
                                         float2* __restrict__ D2, int l)
{
    #pragma unroll 1
    for (int r = 0; r < 16; r++) {
        float a, b;
        mv_core(S, s0, s1, a, b, r);
        D2[r * 8 + l] = make_float2(a, b);
    }
}

__device__ __forceinline__ void mv_addcol(const float* __restrict__ S,
                                          const float* __restrict__ s0,
                                          const float* __restrict__ s1,
                                          float2* __restrict__ D2, int l)
{
    #pragma unroll 1
    for (int r = 0; r < 16; r++) {
        float a, b;
        mv_core(S, s0, s1, a, b, r);
        float2 q = D2[r * 8 + l];
        D2[r * 8 + l] = make_float2(q.x + a, q.y + b);
    }
}

__device__ __forceinline__ float mv_final(const float* __restrict__ S,
                                          const float* __restrict__ s0,
                                          const float* __restrict__ s1,
                                          float2* X2, int l, int c0, int c1)
{
    float tr = 0.f;
    #pragma unroll 1
    for (int r = 0; r < 16; r++) {
        float a, b;
        mv_core(S, s0, s1, a, b, r);
        float2 m = X2[r * 8 + l];
        float ct0 = ((r == c0) ? 1.f : 0.f) + m.x + a;
        float ct1 = ((r == c1) ? 1.f : 0.f) + m.y + b;
        X2[r * 8 + l] = make_float2(ct0, ct1);
        tr = fmaf(ct0, ct0, tr);
        tr = fmaf(ct1, ct1, tr);
    }
    return tr;
}

__global__ __launch_bounds__(128, 6) void psd_expm(
    const float* __restrict__ ldata, float* __restrict__ out)
{
    __shared__ __align__(16) float sh[16 * MST];
    const int tid = threadIdx.x;
    const int g   = tid >> 3;
    const int l   = tid & 7;
    const int b   = blockIdx.x * 16 + g;
    float* X  = sh + g * MST;
    float* T  = X + 256;
    float2* X2 = (float2*)X;
    float2* T2 = (float2*)T;
    const int c0 = 2 * l, c1 = 2 * l + 1;

    const float* rowp = ldata + (size_t)b * CHOL;
    for (int j = l; j < CHOL; j += 8) T[j] = rowp[j];
    __syncwarp();

    float y0[16], y1[16];
    #pragma unroll
    for (int r = 0; r < 16; r++) {
        int hi0 = (r > c0) ? r : c0, lo0 = r + c0 - hi0;
        float v0 = T[hi0 * (hi0 + 1) / 2 + lo0];
        y0[r] = (r == c0) ? 2.f * v0 : v0;
        int hi1 = (r > c1) ? r : c1, lo1 = r + c1 - hi1;
        float v1 = T[hi1 * (hi1 + 1) / 2 + lo1];
        y1[r] = (r == c1) ? 2.f * v1 : v1;
    }
    __syncwarp();
    #pragma unroll
    for (int r = 0; r < 16; r++)
        X2[r * 8 + l] = make_float2(y0[r], y1[r]);   // publish Q
    __syncwarp();

    mv_plain(X, y0, y1, T2, l);                       // T = Q2 cols
    #pragma unroll
    for (int r = 0; r < 16; r++) {
        float2 t = T2[r * 8 + l];
        y0[r] = ((r == c0) ? 1.f : 0.f) + (2.f / 3.f) * y0[r] + (1.f / 3.f) * t.x;
        y1[r] = ((r == c1) ? 1.f : 0.f) + (2.f / 3.f) * y1[r] + (1.f / 3.f) * t.y;
    }
    __syncwarp();                                     // Q2 fully in T

    mv_addcol(T, y0, y1, X2, l);                      // X = M
    #pragma unroll
    for (int r = 0; r < 16; r++) {
        float2 t = X2[r * 8 + l];
        y0[r] = t.x;
        y1[r] = t.y;
    }
    __syncwarp();                                     // M fully in X

    mv_plain(X, y0, y1, T2, l);                       // T = M2 cols
    #pragma unroll
    for (int r = 0; r < 16; r++) {
        float2 t = T2[r * 8 + l];
        y0[r] = ((r == c0) ? 0.5f : 0.f) + (1.f / 6.f) * y0[r] + (1.f / 24.f) * t.x;
        y1[r] = ((r == c1) ? 0.5f : 0.f) + (1.f / 6.f) * y1[r] + (1.f / 24.f) * t.y;
    }
    __syncwarp();                                     // M2 fully in T

    float tr = mv_final(T, y0, y1, X2, l, c0, c1);
    #pragma unroll
    for (int o = 4; o; o >>= 1) tr += __shfl_xor_sync(FULLM, tr, o);
    float scale = rsqrtf(tr);

    float2* op2 = (float2*)(out + (size_t)b * 256);
    #pragma unroll
    for (int r = 0; r < 16; r++) {
        float2 ct = X2[r * 8 + l];
        op2[r * 8 + l] = make_float2(ct.x * scale, ct.y * scale);
    }
}

// ---------------------------------------------------------------------------
extern "C" void kernel_launch(void* const* d_in, const int* in_sizes, int n_in,
                              void* d_out, int out_size)
{
    const float* x  = (const float*)d_in[0];
    const float* W1 = (const float*)d_in[1];
    const float* b1 = (const float*)d_in[2];
    const float* W2 = (const float*)d_in[3];
    const float* b2 = (const float*)d_in[4];
    const float* W3 = (const float*)d_in[5];
    const float* b3 = (const float*)d_in[6];
    float* out = (float*)d_out;

    float *h1, *h2, *ldp;
    float2 *f1, *f2, *f3;
    cudaGetSymbolAddress((void**)&h1,  g_h1);
    cudaGetSymbolAddress((void**)&h2,  g_h2);
    cudaGetSymbolAddress((void**)&ldp, g_ld);
    cudaGetSymbolAddress((void**)&f1,  g_F1);
    cudaGetSymbolAddress((void**)&f2,  g_F2);
    cudaGetSymbolAddress((void**)&f3,  g_F3);

    build_wfrag<<<((IN_DIM/8)*16*32 + 255) / 256, 256>>>(W1, f1, IN_DIM, HID, 16);
    build_wfrag<<<((HID/8)*16*32   + 255) / 256, 256>>>(W2, f2, HID,    HID, 16);
    build_wfrag<<<((HID/8)*17*32   + 255) / 256, 256>>>(W3, f3, HID,   CHOL, 17);

    dim3 blk(256);
    gemm_tf32<0><<<dim3(BATCH / 128, 2), blk>>>(x,  f1, b1, h1,  BATCH, HID,  IN_DIM, 16);
    gemm_tf32<0><<<dim3(BATCH / 128, 2), blk>>>(h1, f2, b2, h2,  BATCH, HID,  HID,    16);
    gemm_tf32<1><<<dim3(BATCH / 128, 3), blk>>>(h2, f3, b3, ldp, BATCH, CHOL, HID,    17);
    psd_expm<<<BATCH / 16, 128>>>(ldp, out);
}